// round 9
// baseline (speedup 1.0000x reference)
#include <cuda_runtime.h>
#include <math.h>

#define T_STEPS 4
#define ROWS    8192      // B*N = 8*1024
#define DDIM    512
#define FDIM    2048
#define MTOT    (T_STEPS*ROWS)   // 32768

typedef unsigned int u32;
typedef unsigned long long u64;

// Scratch (device globals -- no runtime allocation allowed)
__device__ float g_h[(size_t)MTOT * FDIM];        // 256 MiB: layer-1 preacts
__device__ float g_y[(size_t)MTOT * DDIM];        //  64 MiB: layer-2 preacts
__device__ u32   g_mask[(size_t)MTOT * (FDIM/32)];//   8 MiB: spike bitmask

// ---- packed f32x2 helpers ----
__device__ __forceinline__ u64 pack2(float lo, float hi) {
    u64 r; asm("mov.b64 %0, {%1, %2};" : "=l"(r) : "f"(lo), "f"(hi)); return r;
}
__device__ __forceinline__ void unpack2(u64 v, float& lo, float& hi) {
    asm("mov.b64 {%0, %1}, %2;" : "=f"(lo), "=f"(hi) : "l"(v));
}
#define FFMA2(d, a, b) \
    asm("fma.rn.f32x2 %0, %1, %2, %0;" : "+l"(d) : "l"(a), "l"(b))

__device__ __forceinline__ u32 smem_u32(const void* p) {
    u32 a;
    asm("{ .reg .u64 t; cvta.to.shared.u64 t, %1; cvt.u32.u64 %0, t; }" : "=r"(a) : "l"(p));
    return a;
}
__device__ __forceinline__ void cp16(u32 dst, const void* src) {
    asm volatile("cp.async.cg.shared.global [%0], [%1], 16;" :: "r"(dst), "l"(src));
}
#define CP_COMMIT() asm volatile("cp.async.commit_group;" ::: "memory")
#define CP_WAIT(n)  asm volatile("cp.async.wait_group %0;" :: "n"(n) : "memory")

// ---------------------------------------------------------------------------
// GEMM1: R2's 128x128x16 fp32 SGEMM + bias, packed-f32x2 inner loop.
// ---------------------------------------------------------------------------
__global__ __launch_bounds__(256, 2)
void sgemm_bias_128(const float* __restrict__ A, const float* __restrict__ B,
                    const float* __restrict__ bias, float* __restrict__ C,
                    int M, int N, int K) {
    const int BK = 16;
    __shared__ float As[16][128];
    __shared__ float Bs[16][128];

    const int tid = threadIdx.x;
    const int bm  = blockIdx.y * 128;
    const int bn  = blockIdx.x * 128;
    const int tr  = (tid >> 4) * 8;
    const int tc  = (tid & 15) * 8;

    u64 acc[8][4];
#pragma unroll
    for (int i = 0; i < 8; i++)
#pragma unroll
        for (int j = 0; j < 4; j++) acc[i][j] = 0ull;

    const float* Aptr = A + (size_t)bm * K;
    const float* Bptr = B + bn;

    for (int kt = 0; kt < K; kt += BK) {
#pragma unroll
        for (int i = 0; i < 2; i++) {
            int id = tid + i * 256;
            int r  = id >> 2;
            int c4 = (id & 3) << 2;
            float4 v = *(const float4*)(Aptr + (size_t)r * K + kt + c4);
            As[c4 + 0][r] = v.x;
            As[c4 + 1][r] = v.y;
            As[c4 + 2][r] = v.z;
            As[c4 + 3][r] = v.w;
        }
#pragma unroll
        for (int i = 0; i < 2; i++) {
            int id = tid + i * 256;
            int r  = id >> 5;
            int c  = (id & 31) << 2;
            *(float4*)&Bs[r][c] = *(const float4*)(Bptr + (size_t)(kt + r) * N + c);
        }
        __syncthreads();

#pragma unroll
        for (int k = 0; k < BK; k++) {
            float4 av0 = *(const float4*)&As[k][tr];
            float4 av1 = *(const float4*)&As[k][tr + 4];
            u64 a2[8];
            a2[0] = pack2(av0.x, av0.x);
            a2[1] = pack2(av0.y, av0.y);
            a2[2] = pack2(av0.z, av0.z);
            a2[3] = pack2(av0.w, av0.w);
            a2[4] = pack2(av1.x, av1.x);
            a2[5] = pack2(av1.y, av1.y);
            a2[6] = pack2(av1.z, av1.z);
            a2[7] = pack2(av1.w, av1.w);
            const ulonglong2* bp = (const ulonglong2*)&Bs[k][tc];
            ulonglong2 bv0 = bp[0];
            ulonglong2 bv1 = bp[1];
            u64 b2[4] = {bv0.x, bv0.y, bv1.x, bv1.y};

#pragma unroll
            for (int i = 0; i < 8; i++)
#pragma unroll
                for (int j = 0; j < 4; j++)
                    FFMA2(acc[i][j], a2[i], b2[j]);
        }
        __syncthreads();
    }

#pragma unroll
    for (int i = 0; i < 8; i++) {
        float* Crow = C + (size_t)(bm + tr + i) * N + bn + tc;
#pragma unroll
        for (int j = 0; j < 4; j++) {
            float lo, hi;
            unpack2(acc[i][j], lo, hi);
            Crow[2 * j + 0] = lo + bias[bn + tc + 2 * j + 0];
            Crow[2 * j + 1] = hi + bias[bn + tc + 2 * j + 1];
        }
    }
}

// ---------------------------------------------------------------------------
// GEMM2 (sparse-exact): Y[m,:] = b2 + sum_{k: spike(m,k)} W2[k,:]
// Bit-identical to dense k-sequential fp32 GEMM (skipped terms are exact
// no-ops in RN; acc never becomes -0 starting from +0).
// Fixes vs R7/R8:
//  * conflict-free smem: quads permuted at cp.async time so each inner
//    LDS.128 hits lane*16B (consecutive banks, no conflicts)
//  * @p-predicated add.rn.f32x2 per row (no BSSY/BSYNC branch overhead)
//  * __ffs iteration over the 8-row union word (skips dead k, keeps k
//    strictly increasing -> bit-exact order)
// 512 threads. Warp = 8 rows x 256 cols; thread = 8 cols (8x4 u64 acc).
// CTA = 64 rows x 512 cols. W2 streamed via ring-3 of 32-k (64KB) chunks.
// ---------------------------------------------------------------------------
__global__ __launch_bounds__(512)
void spadd_gemm2(const u32* __restrict__ mask, const float* __restrict__ W2,
                 const float* __restrict__ bias, float* __restrict__ Y) {
    extern __shared__ float w2s[];     // 3 * 64 KiB ring, permuted layout

    const int tid  = threadIdx.x;
    const int wid  = tid >> 5;
    const int lane = tid & 31;
    const int grp  = wid >> 1;                    // row-group 0..7
    const int half = wid & 1;                     // col half
    const int m0   = blockIdx.x * 64 + grp * 8;   // warp's 8 rows
    const int c0   = half * 256 + lane * 8;       // thread's 8 cols

    u64 acc[8][4];
#pragma unroll
    for (int r = 0; r < 8; r++)
#pragma unroll
        for (int q = 0; q < 4; q++) acc[r][q] = 0ull;

    const u32 sbase = smem_u32(w2s);

    // chunk c = W2 rows [32c, 32c+32). Permuted placement: quad qg (cols
    // 4qg..4qg+3) of row kk -> kk*2048 + (qg>>6)*1024 + (qg&1)*512 + ((qg>>1)&31)*16
    // so lane l reads its cols [l*8, l*8+8) at lane*16 and lane*16+512.
    auto issue = [&](int c) {
        const u32 slot = sbase + (u32)(c % 3) * 65536u;
#pragma unroll
        for (int j = 0; j < 8; j++) {
            int id = j * 512 + tid;            // 0..4095 quads
            int kk = id >> 7;                  // row in chunk
            int qg = id & 127;                 // quad in row
            const float* src = W2 + ((size_t)(c * 32 + kk) * 512 + qg * 4);
            u32 dst = slot + (u32)kk * 2048u + (u32)(qg >> 6) * 1024u
                           + (u32)(qg & 1) * 512u + (u32)((qg >> 1) & 31) * 16u;
            cp16(dst, src);
        }
        CP_COMMIT();
    };

    issue(0);
    issue(1);

    u32 mrow[8], nm[8];
#pragma unroll
    for (int r = 0; r < 8; r++)
        mrow[r] = mask[(size_t)(m0 + r) * (FDIM / 32)];

    for (int ci = 0; ci < 64; ci++) {
        CP_WAIT(1);
        __syncthreads();                     // chunk ci ready; ci-1 consumers done
        if (ci + 2 < 64) issue(ci + 2);
        if (ci + 1 < 64) {
#pragma unroll
            for (int r = 0; r < 8; r++)
                nm[r] = mask[(size_t)(m0 + r) * (FDIM / 32) + ci + 1];
        }

        u32 u = 0;
#pragma unroll
        for (int r = 0; r < 8; r++) u |= mrow[r];

        const u32 slotb = sbase + (u32)(ci % 3) * 65536u
                        + (u32)half * 1024u + (u32)lane * 16u;
        while (u) {
            const int kk = __ffs(u) - 1;     // lowest set bit -> k increasing
            u &= u - 1;
            const u32 bi = 1u << kk;
            const u32 wb = slotb + (u32)kk * 2048u;
            u64 w0, w1, w2, w3;
            asm volatile("ld.shared.v2.u64 {%0,%1}, [%2];"
                         : "=l"(w0), "=l"(w1) : "r"(wb));
            asm volatile("ld.shared.v2.u64 {%0,%1}, [%2];"
                         : "=l"(w2), "=l"(w3) : "r"(wb + 512u));
#pragma unroll
            for (int r = 0; r < 8; r++) {
                const u32 t = mrow[r] & bi;
                asm("{\n\t.reg .pred p;\n\tsetp.ne.u32 p, %8, 0;\n\t"
                    "@p add.rn.f32x2 %0, %0, %4;\n\t"
                    "@p add.rn.f32x2 %1, %1, %5;\n\t"
                    "@p add.rn.f32x2 %2, %2, %6;\n\t"
                    "@p add.rn.f32x2 %3, %3, %7;\n\t}"
                    : "+l"(acc[r][0]), "+l"(acc[r][1]),
                      "+l"(acc[r][2]), "+l"(acc[r][3])
                    : "l"(w0), "l"(w1), "l"(w2), "l"(w3), "r"(t));
            }
        }
#pragma unroll
        for (int r = 0; r < 8; r++) mrow[r] = nm[r];
    }

    // epilogue: + bias
    float bx[8];
#pragma unroll
    for (int q = 0; q < 2; q++) {
        float4 b4 = *(const float4*)(bias + c0 + q * 4);
        bx[q * 4 + 0] = b4.x; bx[q * 4 + 1] = b4.y;
        bx[q * 4 + 2] = b4.z; bx[q * 4 + 3] = b4.w;
    }
#pragma unroll
    for (int r = 0; r < 8; r++) {
        float* yr = Y + (size_t)(m0 + r) * DDIM + c0;
#pragma unroll
        for (int q = 0; q < 2; q++) {
            float lo0, hi0, lo1, hi1;
            unpack2(acc[r][2 * q + 0], lo0, hi0);
            unpack2(acc[r][2 * q + 1], lo1, hi1);
            float4 o;
            o.x = lo0 + bx[q * 4 + 0];
            o.y = hi0 + bx[q * 4 + 1];
            o.z = lo1 + bx[q * 4 + 2];
            o.w = hi1 + bx[q * 4 + 3];
            *(float4*)(yr + q * 4) = o;
        }
    }
}

// ---------------------------------------------------------------------------
// Block-wide sum reduction
// ---------------------------------------------------------------------------
template <int NT>
__device__ __forceinline__ float block_sum(float val, float* sh) {
    const int lane = threadIdx.x & 31;
    const int warp = threadIdx.x >> 5;
#pragma unroll
    for (int o = 16; o > 0; o >>= 1) val += __shfl_down_sync(0xffffffffu, val, o);
    if (lane == 0) sh[warp] = val;
    __syncthreads();
    const int NW = NT / 32;
    if (warp == 0) {
        float v = (lane < NW) ? sh[lane] : 0.0f;
#pragma unroll
        for (int o = 16; o > 0; o >>= 1) v += __shfl_down_sync(0xffffffffu, v, o);
        if (lane == 0) sh[0] = v;
    }
    __syncthreads();
    float r = sh[0];
    __syncthreads();
    return r;
}

// ---------------------------------------------------------------------------
// Fused LayerNorm + LIF scan. MASK_OUT: emit spike bitmask (layer 1);
// otherwise emit dense float spikes (layer 2 -> d_out).
// ---------------------------------------------------------------------------
template <int FD, int NT, bool MASK_OUT>
__global__ void ln_lif_kernel(const float* __restrict__ in,
                              const float* __restrict__ w,
                              const float* __restrict__ bvec,
                              const float* __restrict__ betap,
                              float* __restrict__ out,
                              u32* __restrict__ maskout) {
    const int VPT = FD / NT;
    const int r   = blockIdx.x;
    const int tid = threadIdx.x;
    const int lane = tid & 31, wid = tid >> 5;
    __shared__ float sh[32];

    float v[T_STEPS][VPT];
    float wv[VPT], bv[VPT];
#pragma unroll
    for (int j = 0; j < VPT; j++) {
        wv[j] = w[tid + j * NT];
        bv[j] = bvec[tid + j * NT];
    }
#pragma unroll
    for (int t = 0; t < T_STEPS; t++) {
        const float* rowp = in + ((size_t)t * ROWS + r) * FD;
#pragma unroll
        for (int j = 0; j < VPT; j++) v[t][j] = rowp[tid + j * NT];
    }

#pragma unroll
    for (int t = 0; t < T_STEPS; t++) {
        float s = 0.0f;
#pragma unroll
        for (int j = 0; j < VPT; j++) s += v[t][j];
        s = block_sum<NT>(s, sh);
        const float mu = s * (1.0f / FD);

        float q = 0.0f;
#pragma unroll
        for (int j = 0; j < VPT; j++) {
            float d = v[t][j] - mu;
            q += d * d;
        }
        q = block_sum<NT>(q, sh);
        const float inv = 1.0f / sqrtf(q * (1.0f / FD) + 1e-5f);

#pragma unroll
        for (int j = 0; j < VPT; j++)
            v[t][j] = (v[t][j] - mu) * inv * wv[j] + bv[j];
    }

    const float beta = *betap;
#pragma unroll
    for (int j = 0; j < VPT; j++) {
        float mem = 0.0f;
#pragma unroll
        for (int t = 0; t < T_STEPS; t++) {
            mem = fmaf(beta, mem, v[t][j]);
            float spk = (mem - 1.0f) > 0.0f ? 1.0f : 0.0f;
            mem -= spk;
            v[t][j] = spk;
        }
    }

#pragma unroll
    for (int t = 0; t < T_STEPS; t++) {
        if (MASK_OUT) {
#pragma unroll
            for (int j = 0; j < VPT; j++) {
                u32 bits = __ballot_sync(0xffffffffu, v[t][j] != 0.0f);
                if (lane == 0)
                    maskout[(size_t)(t * ROWS + r) * (FD / 32) + j * (NT / 32) + wid] = bits;
            }
        } else {
            float* rowp = out + ((size_t)t * ROWS + r) * FD;
#pragma unroll
            for (int j = 0; j < VPT; j++) rowp[tid + j * NT] = v[t][j];
        }
    }
}

// ---------------------------------------------------------------------------
extern "C" void kernel_launch(void* const* d_in, const int* in_sizes, int n_in,
                              void* d_out, int out_size) {
    const float* x     = (const float*)d_in[0];
    const float* W1    = (const float*)d_in[1];
    const float* b1    = (const float*)d_in[2];
    const float* ln1w  = (const float*)d_in[3];
    const float* ln1b  = (const float*)d_in[4];
    const float* beta1 = (const float*)d_in[5];
    const float* W2    = (const float*)d_in[6];
    const float* b2    = (const float*)d_in[7];
    const float* ln2w  = (const float*)d_in[8];
    const float* ln2b  = (const float*)d_in[9];
    const float* beta2 = (const float*)d_in[10];
    float* out = (float*)d_out;

    float *h, *y;
    u32* msk;
    cudaGetSymbolAddress((void**)&h, g_h);
    cudaGetSymbolAddress((void**)&y, g_y);
    cudaGetSymbolAddress((void**)&msk, g_mask);

    // GEMM1: [32768,512] x [512,2048] + b1 -> h
    {
        dim3 grid(FDIM / 128, MTOT / 128);
        sgemm_bias_128<<<grid, 256>>>(x, W1, b1, h, MTOT, FDIM, DDIM);
    }
    // LN1 + LIF1 -> spike bitmask only
    ln_lif_kernel<FDIM, 256, true><<<ROWS, 256>>>(h, ln1w, ln1b, beta1, nullptr, msk);

    // GEMM2 (sparse-exact): mask x W2 + b2 -> y
    const int spadd_smem = 3 * 65536;   // 192 KiB ring
    cudaFuncSetAttribute(spadd_gemm2, cudaFuncAttributeMaxDynamicSharedMemorySize, spadd_smem);
    spadd_gemm2<<<MTOT / 64, 512, spadd_smem>>>(msk, W2, b2, y);

    // LN2 + LIF2 -> d_out
    ln_lif_kernel<DDIM, 128, false><<<ROWS, 128>>>(y, ln2w, ln2b, beta2, out, nullptr);
}

// round 10
// speedup vs baseline: 1.3189x; 1.3189x over previous
#include <cuda_runtime.h>
#include <math.h>

#define T_STEPS 4
#define ROWS    8192      // B*N = 8*1024
#define DDIM    512
#define FDIM    2048
#define MTOT    (T_STEPS*ROWS)   // 32768

typedef unsigned long long u64;

// Scratch (device globals -- no runtime allocation allowed)
__device__ float g_h[(size_t)MTOT * FDIM];   // 256 MiB: hidden acts / spikes
__device__ float g_y[(size_t)MTOT * DDIM];   //  64 MiB: layer-2 preacts

// ---- packed f32x2 helpers (sm_100+: fma.rn.f32x2; ptxas never emits it) ----
__device__ __forceinline__ u64 pack2(float lo, float hi) {
    u64 r; asm("mov.b64 %0, {%1, %2};" : "=l"(r) : "f"(lo), "f"(hi)); return r;
}
__device__ __forceinline__ void unpack2(u64 v, float& lo, float& hi) {
    asm("mov.b64 {%0, %1}, %2;" : "=f"(lo), "=f"(hi) : "l"(v));
}
#define FFMA2(d, a, b) \
    asm("fma.rn.f32x2 %0, %1, %2, %0;" : "+l"(d) : "l"(a), "l"(b))

// ---------------------------------------------------------------------------
// 128x128x32 fp32 SGEMM with fused bias, packed-f32x2 inner loop.
// C[M,N] = A[M,K]*B[K,N] + bias. 256 threads, 8x8 per thread (8x4 f32x2).
// BK=32 (vs R2's 16): half the __syncthreads per unit work. k is strictly
// sequential per output -> accumulation trajectory bit-identical to R2.
// ---------------------------------------------------------------------------
__global__ __launch_bounds__(256, 2)
void sgemm_bias_128(const float* __restrict__ A, const float* __restrict__ B,
                    const float* __restrict__ bias, float* __restrict__ C,
                    int M, int N, int K) {
    const int BK = 32;
    __shared__ float As[32][128];   // 16 KiB
    __shared__ float Bs[32][128];   // 16 KiB

    const int tid = threadIdx.x;
    const int bm  = blockIdx.y * 128;
    const int bn  = blockIdx.x * 128;
    const int tr  = (tid >> 4) * 8;   // 0..120
    const int tc  = (tid & 15) * 8;   // 0..120

    u64 acc[8][4];
#pragma unroll
    for (int i = 0; i < 8; i++)
#pragma unroll
        for (int j = 0; j < 4; j++) acc[i][j] = 0ull;

    const float* Aptr = A + (size_t)bm * K;
    const float* Bptr = B + bn;

    for (int kt = 0; kt < K; kt += BK) {
        // Load A tile 128x32 (1024 float4), transposed into As[k][m]
#pragma unroll
        for (int i = 0; i < 4; i++) {
            int id = tid + i * 256;
            int r  = id >> 3;
            int c4 = (id & 7) << 2;
            float4 v = *(const float4*)(Aptr + (size_t)r * K + kt + c4);
            As[c4 + 0][r] = v.x;
            As[c4 + 1][r] = v.y;
            As[c4 + 2][r] = v.z;
            As[c4 + 3][r] = v.w;
        }
        // Load B tile 32x128 (1024 float4), direct
#pragma unroll
        for (int i = 0; i < 4; i++) {
            int id = tid + i * 256;
            int r  = id >> 5;
            int c  = (id & 31) << 2;
            *(float4*)&Bs[r][c] = *(const float4*)(Bptr + (size_t)(kt + r) * N + c);
        }
        __syncthreads();

#pragma unroll
        for (int k = 0; k < BK; k++) {
            // A fragment: 8 scalars, broadcast-packed into f32x2
            float4 av0 = *(const float4*)&As[k][tr];
            float4 av1 = *(const float4*)&As[k][tr + 4];
            u64 a2[8];
            a2[0] = pack2(av0.x, av0.x);
            a2[1] = pack2(av0.y, av0.y);
            a2[2] = pack2(av0.z, av0.z);
            a2[3] = pack2(av0.w, av0.w);
            a2[4] = pack2(av1.x, av1.x);
            a2[5] = pack2(av1.y, av1.y);
            a2[6] = pack2(av1.z, av1.z);
            a2[7] = pack2(av1.w, av1.w);
            // B fragment: 4 packed pairs (contiguous, already interleaved right)
            const ulonglong2* bp = (const ulonglong2*)&Bs[k][tc];
            ulonglong2 bv0 = bp[0];
            ulonglong2 bv1 = bp[1];
            u64 b2[4] = {bv0.x, bv0.y, bv1.x, bv1.y};

#pragma unroll
            for (int i = 0; i < 8; i++)
#pragma unroll
                for (int j = 0; j < 4; j++)
                    FFMA2(acc[i][j], a2[i], b2[j]);
        }
        __syncthreads();
    }

#pragma unroll
    for (int i = 0; i < 8; i++) {
        float* Crow = C + (size_t)(bm + tr + i) * N + bn + tc;
#pragma unroll
        for (int j = 0; j < 4; j++) {
            float lo, hi;
            unpack2(acc[i][j], lo, hi);
            Crow[2 * j + 0] = lo + bias[bn + tc + 2 * j + 0];
            Crow[2 * j + 1] = hi + bias[bn + tc + 2 * j + 1];
        }
    }
}

// ---------------------------------------------------------------------------
// Block-wide sum reduction
// ---------------------------------------------------------------------------
template <int NT>
__device__ __forceinline__ float block_sum(float val, float* sh) {
    const int lane = threadIdx.x & 31;
    const int warp = threadIdx.x >> 5;
#pragma unroll
    for (int o = 16; o > 0; o >>= 1) val += __shfl_down_sync(0xffffffffu, val, o);
    if (lane == 0) sh[warp] = val;
    __syncthreads();
    const int NW = NT / 32;
    if (warp == 0) {
        float v = (lane < NW) ? sh[lane] : 0.0f;
#pragma unroll
        for (int o = 16; o > 0; o >>= 1) v += __shfl_down_sync(0xffffffffu, v, o);
        if (lane == 0) sh[0] = v;
    }
    __syncthreads();
    float r = sh[0];
    __syncthreads();
    return r;
}

// ---------------------------------------------------------------------------
// Fused LayerNorm (per row, per t) + LIF scan across T (in registers).
// ---------------------------------------------------------------------------
template <int FD, int NT>
__global__ void ln_lif_kernel(const float* __restrict__ in,
                              const float* __restrict__ w,
                              const float* __restrict__ bvec,
                              const float* __restrict__ betap,
                              float* __restrict__ out) {
    const int VPT = FD / NT;
    const int r   = blockIdx.x;
    const int tid = threadIdx.x;
    __shared__ float sh[32];

    float v[T_STEPS][VPT];
    float wv[VPT], bv[VPT];
#pragma unroll
    for (int j = 0; j < VPT; j++) {
        wv[j] = w[tid + j * NT];
        bv[j] = bvec[tid + j * NT];
    }
#pragma unroll
    for (int t = 0; t < T_STEPS; t++) {
        const float* rowp = in + ((size_t)t * ROWS + r) * FD;
#pragma unroll
        for (int j = 0; j < VPT; j++) v[t][j] = rowp[tid + j * NT];
    }

#pragma unroll
    for (int t = 0; t < T_STEPS; t++) {
        float s = 0.0f;
#pragma unroll
        for (int j = 0; j < VPT; j++) s += v[t][j];
        s = block_sum<NT>(s, sh);
        const float mu = s * (1.0f / FD);

        float q = 0.0f;
#pragma unroll
        for (int j = 0; j < VPT; j++) {
            float d = v[t][j] - mu;
            q += d * d;
        }
        q = block_sum<NT>(q, sh);
        const float inv = 1.0f / sqrtf(q * (1.0f / FD) + 1e-5f);

#pragma unroll
        for (int j = 0; j < VPT; j++)
            v[t][j] = (v[t][j] - mu) * inv * wv[j] + bv[j];
    }

    // LIF scan across T in registers (soft reset, threshold 1.0)
    const float beta = *betap;
#pragma unroll
    for (int j = 0; j < VPT; j++) {
        float mem = 0.0f;
#pragma unroll
        for (int t = 0; t < T_STEPS; t++) {
            mem = fmaf(beta, mem, v[t][j]);
            float spk = (mem - 1.0f) > 0.0f ? 1.0f : 0.0f;
            mem -= spk;
            v[t][j] = spk;
        }
    }

#pragma unroll
    for (int t = 0; t < T_STEPS; t++) {
        float* rowp = out + ((size_t)t * ROWS + r) * FD;
#pragma unroll
        for (int j = 0; j < VPT; j++) rowp[tid + j * NT] = v[t][j];
    }
}

// ---------------------------------------------------------------------------
extern "C" void kernel_launch(void* const* d_in, const int* in_sizes, int n_in,
                              void* d_out, int out_size) {
    const float* x     = (const float*)d_in[0];
    const float* W1    = (const float*)d_in[1];
    const float* b1    = (const float*)d_in[2];
    const float* ln1w  = (const float*)d_in[3];
    const float* ln1b  = (const float*)d_in[4];
    const float* beta1 = (const float*)d_in[5];
    const float* W2    = (const float*)d_in[6];
    const float* b2    = (const float*)d_in[7];
    const float* ln2w  = (const float*)d_in[8];
    const float* ln2b  = (const float*)d_in[9];
    const float* beta2 = (const float*)d_in[10];
    float* out = (float*)d_out;

    float *h, *y;
    cudaGetSymbolAddress((void**)&h, g_h);
    cudaGetSymbolAddress((void**)&y, g_y);

    // GEMM1: [32768,512] x [512,2048] + b1 -> h
    {
        dim3 grid(FDIM / 128, MTOT / 128);
        sgemm_bias_128<<<grid, 256>>>(x, W1, b1, h, MTOT, FDIM, DDIM);
    }
    // LN1 + LIF1 (in place: h preacts -> h spikes)
    ln_lif_kernel<FDIM, 256><<<ROWS, 256>>>(h, ln1w, ln1b, beta1, h);

    // GEMM2: [32768,2048] x [2048,512] + b2 -> y
    {
        dim3 grid(DDIM / 128, MTOT / 128);
        sgemm_bias_128<<<grid, 256>>>(h, W2, b2, y, MTOT, DDIM, FDIM);
    }
    // LN2 + LIF2 -> d_out
    ln_lif_kernel<DDIM, 128><<<ROWS, 128>>>(y, ln2w, ln2b, beta2, out);
}

// round 11
// speedup vs baseline: 1.3898x; 1.0537x over previous
#include <cuda_runtime.h>
#include <math.h>

#define T_STEPS 4
#define ROWS    8192      // B*N = 8*1024
#define DDIM    512
#define FDIM    2048
#define MTOT    (T_STEPS*ROWS)   // 32768

typedef unsigned long long u64;

// Scratch (device globals -- no runtime allocation allowed)
__device__ float g_h[(size_t)MTOT * FDIM];   // 256 MiB: hidden acts / spikes
__device__ float g_y[(size_t)MTOT * DDIM];   //  64 MiB: layer-2 preacts

// ---- packed f32x2 helpers (sm_100+: fma.rn.f32x2; ptxas never emits it) ----
__device__ __forceinline__ u64 pack2(float lo, float hi) {
    u64 r; asm("mov.b64 %0, {%1, %2};" : "=l"(r) : "f"(lo), "f"(hi)); return r;
}
__device__ __forceinline__ void unpack2(u64 v, float& lo, float& hi) {
    asm("mov.b64 {%0, %1}, %2;" : "=f"(lo), "=f"(hi) : "l"(v));
}
#define FFMA2(d, a, b) \
    asm("fma.rn.f32x2 %0, %1, %2, %0;" : "+l"(d) : "l"(a), "l"(b))

// ---------------------------------------------------------------------------
// 128x128x16 fp32 SGEMM with fused bias, packed-f32x2 inner loop (R2 layout).
// C[M,N] = A[M,K]*B[K,N] + bias. 256 threads, 8x8 per thread (8x4 f32x2).
// Change vs R2: As row stride padded 128 -> 132 floats, reducing the 4-way
// bank conflicts on transposed A-staging stores to 2-way. Reads stay aligned
// (528B row stride; tr multiple of 8). Accumulation trajectory unchanged.
// ---------------------------------------------------------------------------
__global__ __launch_bounds__(256, 2)
void sgemm_bias_128(const float* __restrict__ A, const float* __restrict__ B,
                    const float* __restrict__ bias, float* __restrict__ C,
                    int M, int N, int K) {
    const int BK = 16;
    const int AP = 132;              // padded A row stride (floats)
    __shared__ float As[16 * 132];   // ~8.25 KiB
    __shared__ float Bs[16][128];    //  8 KiB

    const int tid = threadIdx.x;
    const int bm  = blockIdx.y * 128;
    const int bn  = blockIdx.x * 128;
    const int tr  = (tid >> 4) * 8;   // 0..120
    const int tc  = (tid & 15) * 8;   // 0..120

    u64 acc[8][4];
#pragma unroll
    for (int i = 0; i < 8; i++)
#pragma unroll
        for (int j = 0; j < 4; j++) acc[i][j] = 0ull;

    const float* Aptr = A + (size_t)bm * K;
    const float* Bptr = B + bn;

    for (int kt = 0; kt < K; kt += BK) {
        // Load A tile 128x16 (512 float4), transposed into As[k*AP + m]
#pragma unroll
        for (int i = 0; i < 2; i++) {
            int id = tid + i * 256;
            int r  = id >> 2;
            int c4 = (id & 3) << 2;
            float4 v = *(const float4*)(Aptr + (size_t)r * K + kt + c4);
            As[(c4 + 0) * AP + r] = v.x;
            As[(c4 + 1) * AP + r] = v.y;
            As[(c4 + 2) * AP + r] = v.z;
            As[(c4 + 3) * AP + r] = v.w;
        }
        // Load B tile 16x128 (512 float4), direct
#pragma unroll
        for (int i = 0; i < 2; i++) {
            int id = tid + i * 256;
            int r  = id >> 5;
            int c  = (id & 31) << 2;
            *(float4*)&Bs[r][c] = *(const float4*)(Bptr + (size_t)(kt + r) * N + c);
        }
        __syncthreads();

#pragma unroll
        for (int k = 0; k < BK; k++) {
            // A fragment: 8 scalars, broadcast-packed into f32x2
            float4 av0 = *(const float4*)&As[k * AP + tr];
            float4 av1 = *(const float4*)&As[k * AP + tr + 4];
            u64 a2[8];
            a2[0] = pack2(av0.x, av0.x);
            a2[1] = pack2(av0.y, av0.y);
            a2[2] = pack2(av0.z, av0.z);
            a2[3] = pack2(av0.w, av0.w);
            a2[4] = pack2(av1.x, av1.x);
            a2[5] = pack2(av1.y, av1.y);
            a2[6] = pack2(av1.z, av1.z);
            a2[7] = pack2(av1.w, av1.w);
            // B fragment: 4 packed pairs (contiguous, already interleaved right)
            const ulonglong2* bp = (const ulonglong2*)&Bs[k][tc];
            ulonglong2 bv0 = bp[0];
            ulonglong2 bv1 = bp[1];
            u64 b2[4] = {bv0.x, bv0.y, bv1.x, bv1.y};

#pragma unroll
            for (int i = 0; i < 8; i++)
#pragma unroll
                for (int j = 0; j < 4; j++)
                    FFMA2(acc[i][j], a2[i], b2[j]);
        }
        __syncthreads();
    }

#pragma unroll
    for (int i = 0; i < 8; i++) {
        float* Crow = C + (size_t)(bm + tr + i) * N + bn + tc;
#pragma unroll
        for (int j = 0; j < 4; j++) {
            float lo, hi;
            unpack2(acc[i][j], lo, hi);
            Crow[2 * j + 0] = lo + bias[bn + tc + 2 * j + 0];
            Crow[2 * j + 1] = hi + bias[bn + tc + 2 * j + 1];
        }
    }
}

// ---------------------------------------------------------------------------
// Block-wide sum reduction
// ---------------------------------------------------------------------------
template <int NT>
__device__ __forceinline__ float block_sum(float val, float* sh) {
    const int lane = threadIdx.x & 31;
    const int warp = threadIdx.x >> 5;
#pragma unroll
    for (int o = 16; o > 0; o >>= 1) val += __shfl_down_sync(0xffffffffu, val, o);
    if (lane == 0) sh[warp] = val;
    __syncthreads();
    const int NW = NT / 32;
    if (warp == 0) {
        float v = (lane < NW) ? sh[lane] : 0.0f;
#pragma unroll
        for (int o = 16; o > 0; o >>= 1) v += __shfl_down_sync(0xffffffffu, v, o);
        if (lane == 0) sh[0] = v;
    }
    __syncthreads();
    float r = sh[0];
    __syncthreads();
    return r;
}

// ---------------------------------------------------------------------------
// Fused LayerNorm (per row, per t) + LIF scan across T (in registers).
// ---------------------------------------------------------------------------
template <int FD, int NT>
__global__ void ln_lif_kernel(const float* __restrict__ in,
                              const float* __restrict__ w,
                              const float* __restrict__ bvec,
                              const float* __restrict__ betap,
                              float* __restrict__ out) {
    const int VPT = FD / NT;
    const int r   = blockIdx.x;
    const int tid = threadIdx.x;
    __shared__ float sh[32];

    float v[T_STEPS][VPT];
    float wv[VPT], bv[VPT];
#pragma unroll
    for (int j = 0; j < VPT; j++) {
        wv[j] = w[tid + j * NT];
        bv[j] = bvec[tid + j * NT];
    }
#pragma unroll
    for (int t = 0; t < T_STEPS; t++) {
        const float* rowp = in + ((size_t)t * ROWS + r) * FD;
#pragma unroll
        for (int j = 0; j < VPT; j++) v[t][j] = rowp[tid + j * NT];
    }

#pragma unroll
    for (int t = 0; t < T_STEPS; t++) {
        float s = 0.0f;
#pragma unroll
        for (int j = 0; j < VPT; j++) s += v[t][j];
        s = block_sum<NT>(s, sh);
        const float mu = s * (1.0f / FD);

        float q = 0.0f;
#pragma unroll
        for (int j = 0; j < VPT; j++) {
            float d = v[t][j] - mu;
            q += d * d;
        }
        q = block_sum<NT>(q, sh);
        const float inv = 1.0f / sqrtf(q * (1.0f / FD) + 1e-5f);

#pragma unroll
        for (int j = 0; j < VPT; j++)
            v[t][j] = (v[t][j] - mu) * inv * wv[j] + bv[j];
    }

    // LIF scan across T in registers (soft reset, threshold 1.0)
    const float beta = *betap;
#pragma unroll
    for (int j = 0; j < VPT; j++) {
        float mem = 0.0f;
#pragma unroll
        for (int t = 0; t < T_STEPS; t++) {
            mem = fmaf(beta, mem, v[t][j]);
            float spk = (mem - 1.0f) > 0.0f ? 1.0f : 0.0f;
            mem -= spk;
            v[t][j] = spk;
        }
    }

#pragma unroll
    for (int t = 0; t < T_STEPS; t++) {
        float* rowp = out + ((size_t)t * ROWS + r) * FD;
#pragma unroll
        for (int j = 0; j < VPT; j++) rowp[tid + j * NT] = v[t][j];
    }
}

// ---------------------------------------------------------------------------
extern "C" void kernel_launch(void* const* d_in, const int* in_sizes, int n_in,
                              void* d_out, int out_size) {
    const float* x     = (const float*)d_in[0];
    const float* W1    = (const float*)d_in[1];
    const float* b1    = (const float*)d_in[2];
    const float* ln1w  = (const float*)d_in[3];
    const float* ln1b  = (const float*)d_in[4];
    const float* beta1 = (const float*)d_in[5];
    const float* W2    = (const float*)d_in[6];
    const float* b2    = (const float*)d_in[7];
    const float* ln2w  = (const float*)d_in[8];
    const float* ln2b  = (const float*)d_in[9];
    const float* beta2 = (const float*)d_in[10];
    float* out = (float*)d_out;

    float *h, *y;
    cudaGetSymbolAddress((void**)&h, g_h);
    cudaGetSymbolAddress((void**)&y, g_y);

    // GEMM1: [32768,512] x [512,2048] + b1 -> h
    {
        dim3 grid(FDIM / 128, MTOT / 128);
        sgemm_bias_128<<<grid, 256>>>(x, W1, b1, h, MTOT, FDIM, DDIM);
    }
    // LN1 + LIF1 (in place: h preacts -> h spikes)
    ln_lif_kernel<FDIM, 256><<<ROWS, 256>>>(h, ln1w, ln1b, beta1, h);

    // GEMM2: [32768,2048] x [2048,512] + b2 -> y
    {
        dim3 grid(DDIM / 128, MTOT / 128);
        sgemm_bias_128<<<grid, 256>>>(h, W2, b2, y, MTOT, DDIM, FDIM);
    }
    // LN2 + LIF2 -> d_out
    ln_lif_kernel<DDIM, 128><<<ROWS, 128>>>(y, ln2w, ln2b, beta2, out);
}

// round 12
// speedup vs baseline: 1.4301x; 1.0290x over previous
#include <cuda_runtime.h>
#include <math.h>

#define T_STEPS 4
#define ROWS    8192      // B*N = 8*1024
#define DDIM    512
#define FDIM    2048
#define MTOT    (T_STEPS*ROWS)   // 32768

typedef unsigned int u32;
typedef unsigned long long u64;

// Scratch (device globals -- no runtime allocation allowed)
__device__ float g_h[(size_t)MTOT * FDIM];         // 256 MiB: layer-1 preacts
__device__ float g_y[(size_t)MTOT * DDIM];         //  64 MiB: layer-2 preacts
__device__ u32   g_mask[(size_t)MTOT * (FDIM/32)]; //   8 MiB: spike bitmask

// ---- packed f32x2 helpers (sm_100+: fma.rn.f32x2; ptxas never emits it) ----
__device__ __forceinline__ u64 pack2(float lo, float hi) {
    u64 r; asm("mov.b64 %0, {%1, %2};" : "=l"(r) : "f"(lo), "f"(hi)); return r;
}
__device__ __forceinline__ void unpack2(u64 v, float& lo, float& hi) {
    asm("mov.b64 {%0, %1}, %2;" : "=f"(lo), "=f"(hi) : "l"(v));
}
#define FFMA2(d, a, b) \
    asm("fma.rn.f32x2 %0, %1, %2, %0;" : "+l"(d) : "l"(a), "l"(b))

// ---------------------------------------------------------------------------
// 128x128x16 fp32 SGEMM with fused bias, packed-f32x2 inner loop.
// MASK_A=false: A from dense floats (GEMM1).
// MASK_A=true : A reconstructed from spike bitmask as exact 1.0f/0.0f
//               (GEMM2) -- identical values, identical FFMA2 trajectory.
// As row stride padded to 132 floats (R11's store-conflict fix).
// ---------------------------------------------------------------------------
template <bool MASK_A>
__global__ __launch_bounds__(256, 2)
void sgemm_bias_128(const float* __restrict__ A, const u32* __restrict__ Amask,
                    const float* __restrict__ B,
                    const float* __restrict__ bias, float* __restrict__ C,
                    int M, int N, int K) {
    const int BK = 16;
    const int AP = 132;              // padded A row stride (floats)
    __shared__ float As[16 * 132];   // ~8.25 KiB
    __shared__ float Bs[16][128];    //  8 KiB

    const int tid = threadIdx.x;
    const int bm  = blockIdx.y * 128;
    const int bn  = blockIdx.x * 128;
    const int tr  = (tid >> 4) * 8;   // 0..120
    const int tc  = (tid & 15) * 8;   // 0..120

    u64 acc[8][4];
#pragma unroll
    for (int i = 0; i < 8; i++)
#pragma unroll
        for (int j = 0; j < 4; j++) acc[i][j] = 0ull;

    const float* Aptr = A + (size_t)bm * K;
    const float* Bptr = B + bn;

    for (int kt = 0; kt < K; kt += BK) {
        // Stage A tile 128x16, transposed into As[k*AP + m]
#pragma unroll
        for (int i = 0; i < 2; i++) {
            int id = tid + i * 256;
            int r  = id >> 2;
            int c4 = (id & 3) << 2;
            if (MASK_A) {
                // spikes: 1 bit each, expand to exact 1.0f / 0.0f
                u32 w = Amask[(size_t)(bm + r) * (K / 32) + (kt >> 5)];
                int sh = (kt & 31) + c4;
                As[(c4 + 0) * AP + r] = ((w >> (sh + 0)) & 1u) ? 1.0f : 0.0f;
                As[(c4 + 1) * AP + r] = ((w >> (sh + 1)) & 1u) ? 1.0f : 0.0f;
                As[(c4 + 2) * AP + r] = ((w >> (sh + 2)) & 1u) ? 1.0f : 0.0f;
                As[(c4 + 3) * AP + r] = ((w >> (sh + 3)) & 1u) ? 1.0f : 0.0f;
            } else {
                float4 v = *(const float4*)(Aptr + (size_t)r * K + kt + c4);
                As[(c4 + 0) * AP + r] = v.x;
                As[(c4 + 1) * AP + r] = v.y;
                As[(c4 + 2) * AP + r] = v.z;
                As[(c4 + 3) * AP + r] = v.w;
            }
        }
        // Load B tile 16x128 (512 float4), direct
#pragma unroll
        for (int i = 0; i < 2; i++) {
            int id = tid + i * 256;
            int r  = id >> 5;
            int c  = (id & 31) << 2;
            *(float4*)&Bs[r][c] = *(const float4*)(Bptr + (size_t)(kt + r) * N + c);
        }
        __syncthreads();

#pragma unroll
        for (int k = 0; k < BK; k++) {
            float4 av0 = *(const float4*)&As[k * AP + tr];
            float4 av1 = *(const float4*)&As[k * AP + tr + 4];
            u64 a2[8];
            a2[0] = pack2(av0.x, av0.x);
            a2[1] = pack2(av0.y, av0.y);
            a2[2] = pack2(av0.z, av0.z);
            a2[3] = pack2(av0.w, av0.w);
            a2[4] = pack2(av1.x, av1.x);
            a2[5] = pack2(av1.y, av1.y);
            a2[6] = pack2(av1.z, av1.z);
            a2[7] = pack2(av1.w, av1.w);
            const ulonglong2* bp = (const ulonglong2*)&Bs[k][tc];
            ulonglong2 bv0 = bp[0];
            ulonglong2 bv1 = bp[1];
            u64 b2[4] = {bv0.x, bv0.y, bv1.x, bv1.y};

#pragma unroll
            for (int i = 0; i < 8; i++)
#pragma unroll
                for (int j = 0; j < 4; j++)
                    FFMA2(acc[i][j], a2[i], b2[j]);
        }
        __syncthreads();
    }

#pragma unroll
    for (int i = 0; i < 8; i++) {
        float* Crow = C + (size_t)(bm + tr + i) * N + bn + tc;
#pragma unroll
        for (int j = 0; j < 4; j++) {
            float lo, hi;
            unpack2(acc[i][j], lo, hi);
            Crow[2 * j + 0] = lo + bias[bn + tc + 2 * j + 0];
            Crow[2 * j + 1] = hi + bias[bn + tc + 2 * j + 1];
        }
    }
}

// ---------------------------------------------------------------------------
// Block-wide sum reduction
// ---------------------------------------------------------------------------
template <int NT>
__device__ __forceinline__ float block_sum(float val, float* sh) {
    const int lane = threadIdx.x & 31;
    const int warp = threadIdx.x >> 5;
#pragma unroll
    for (int o = 16; o > 0; o >>= 1) val += __shfl_down_sync(0xffffffffu, val, o);
    if (lane == 0) sh[warp] = val;
    __syncthreads();
    const int NW = NT / 32;
    if (warp == 0) {
        float v = (lane < NW) ? sh[lane] : 0.0f;
#pragma unroll
        for (int o = 16; o > 0; o >>= 1) v += __shfl_down_sync(0xffffffffu, v, o);
        if (lane == 0) sh[0] = v;
    }
    __syncthreads();
    float r = sh[0];
    __syncthreads();
    return r;
}

// ---------------------------------------------------------------------------
// Fused LayerNorm + LIF scan. MASK_OUT: emit spike bitmask only (layer 1,
// saves the 256 MiB dense-spike write); else dense float out (layer 2).
// Mask layout is linear in feature index: word w covers features
// [w*32, w*32+32) of its row (j*8+wid == f_base/32 for NT=256).
// ---------------------------------------------------------------------------
template <int FD, int NT, bool MASK_OUT>
__global__ void ln_lif_kernel(const float* __restrict__ in,
                              const float* __restrict__ w,
                              const float* __restrict__ bvec,
                              const float* __restrict__ betap,
                              float* __restrict__ out,
                              u32* __restrict__ maskout) {
    const int VPT = FD / NT;
    const int r   = blockIdx.x;
    const int tid = threadIdx.x;
    const int lane = tid & 31, wid = tid >> 5;
    __shared__ float sh[32];

    float v[T_STEPS][VPT];
    float wv[VPT], bv[VPT];
#pragma unroll
    for (int j = 0; j < VPT; j++) {
        wv[j] = w[tid + j * NT];
        bv[j] = bvec[tid + j * NT];
    }
#pragma unroll
    for (int t = 0; t < T_STEPS; t++) {
        const float* rowp = in + ((size_t)t * ROWS + r) * FD;
#pragma unroll
        for (int j = 0; j < VPT; j++) v[t][j] = rowp[tid + j * NT];
    }

#pragma unroll
    for (int t = 0; t < T_STEPS; t++) {
        float s = 0.0f;
#pragma unroll
        for (int j = 0; j < VPT; j++) s += v[t][j];
        s = block_sum<NT>(s, sh);
        const float mu = s * (1.0f / FD);

        float q = 0.0f;
#pragma unroll
        for (int j = 0; j < VPT; j++) {
            float d = v[t][j] - mu;
            q += d * d;
        }
        q = block_sum<NT>(q, sh);
        const float inv = 1.0f / sqrtf(q * (1.0f / FD) + 1e-5f);

#pragma unroll
        for (int j = 0; j < VPT; j++)
            v[t][j] = (v[t][j] - mu) * inv * wv[j] + bv[j];
    }

    const float beta = *betap;
#pragma unroll
    for (int j = 0; j < VPT; j++) {
        float mem = 0.0f;
#pragma unroll
        for (int t = 0; t < T_STEPS; t++) {
            mem = fmaf(beta, mem, v[t][j]);
            float spk = (mem - 1.0f) > 0.0f ? 1.0f : 0.0f;
            mem -= spk;
            v[t][j] = spk;
        }
    }

#pragma unroll
    for (int t = 0; t < T_STEPS; t++) {
        if (MASK_OUT) {
#pragma unroll
            for (int j = 0; j < VPT; j++) {
                u32 bits = __ballot_sync(0xffffffffu, v[t][j] != 0.0f);
                if (lane == 0)
                    maskout[(size_t)(t * ROWS + r) * (FD / 32) + j * (NT / 32) + wid] = bits;
            }
        } else {
            float* rowp = out + ((size_t)t * ROWS + r) * FD;
#pragma unroll
            for (int j = 0; j < VPT; j++) rowp[tid + j * NT] = v[t][j];
        }
    }
}

// ---------------------------------------------------------------------------
extern "C" void kernel_launch(void* const* d_in, const int* in_sizes, int n_in,
                              void* d_out, int out_size) {
    const float* x     = (const float*)d_in[0];
    const float* W1    = (const float*)d_in[1];
    const float* b1    = (const float*)d_in[2];
    const float* ln1w  = (const float*)d_in[3];
    const float* ln1b  = (const float*)d_in[4];
    const float* beta1 = (const float*)d_in[5];
    const float* W2    = (const float*)d_in[6];
    const float* b2    = (const float*)d_in[7];
    const float* ln2w  = (const float*)d_in[8];
    const float* ln2b  = (const float*)d_in[9];
    const float* beta2 = (const float*)d_in[10];
    float* out = (float*)d_out;

    float *h, *y;
    u32* msk;
    cudaGetSymbolAddress((void**)&h, g_h);
    cudaGetSymbolAddress((void**)&y, g_y);
    cudaGetSymbolAddress((void**)&msk, g_mask);

    // GEMM1: [32768,512] x [512,2048] + b1 -> h   (dense A)
    {
        dim3 grid(FDIM / 128, MTOT / 128);
        sgemm_bias_128<false><<<grid, 256>>>(x, nullptr, W1, b1, h, MTOT, FDIM, DDIM);
    }
    // LN1 + LIF1 -> 8 MiB spike bitmask (no dense spike write)
    ln_lif_kernel<FDIM, 256, true><<<ROWS, 256>>>(h, ln1w, ln1b, beta1, nullptr, msk);

    // GEMM2: spikes(mask) x [2048,512] + b2 -> y  (A expanded from bits)
    {
        dim3 grid(DDIM / 128, MTOT / 128);
        sgemm_bias_128<true><<<grid, 256>>>(nullptr, msk, W2, b2, y, MTOT, DDIM, FDIM);
    }
    // LN2 + LIF2 -> d_out
    ln_lif_kernel<DDIM, 128, false><<<ROWS, 128>>>(y, ln2w, ln2b, beta2, out, nullptr);
}